// round 5
// baseline (speedup 1.0000x reference)
#include <cuda_runtime.h>
#include <cuda_fp16.h>

#define N_NODES 100000
#define N_EDGES 1000000
#define NB_SCAN 98      // ceil(100000 / 1024)

__device__ __half g_t[N_NODES * 64];     // [n][o][c] fp16
__device__ __half g_tb[N_NODES * 16];    // [n][o]    fp16
__device__ float  g_r[N_NODES * 16];     // [n][o]    fp32: v@root + bias
__device__ int    g_deg[N_NODES];
__device__ int    g_rowstart[N_NODES];
__device__ int    g_cursor[N_NODES];
__device__ int    g_blocksum[NB_SCAN];
__device__ uint2  g_perm[N_EDGES];       // {src, eid} sorted by dst
__device__ float  g_s1[16];
__device__ float  g_s2[16];

// ---------------------------------------------------------------------------
// K0: zero degree histogram + BN stats
// ---------------------------------------------------------------------------
__global__ void __launch_bounds__(256) k_zero() {
    int idx = blockIdx.x * 256 + threadIdx.x;
    if (idx < N_NODES) g_deg[idx] = 0;
    if (idx < 16) { g_s1[idx] = 0.0f; g_s2[idx] = 0.0f; }
}

// ---------------------------------------------------------------------------
// K1: per-node precompute of t (fp16), tb (fp16), r = v@root + bias (fp32).
// ---------------------------------------------------------------------------
__global__ void __launch_bounds__(256) k_node_pre(
    const float* __restrict__ v,
    const float* __restrict__ enet_w,   // [256][4]
    const float* __restrict__ enet_b,   // [256]
    const float* __restrict__ root,     // [16][16] (i,o)
    const float* __restrict__ bias)     // [16]
{
    __shared__ float sw[1024];
    __shared__ float sb[256];
    __shared__ float sroot[256];
    __shared__ float sv[256];
    int t = threadIdx.x;
    for (int i = t; i < 1024; i += 256) sw[i] = enet_w[i];
    sb[t] = enet_b[t];
    sroot[t] = root[t];
    int nbase = blockIdx.x * 16;
    sv[t] = v[nbase * 16 + t];
    __syncthreads();

    int nl = t >> 4;
    int o = t & 15;
    int n = nbase + nl;
    if (n >= N_NODES) return;

    float a0 = 0.f, a1 = 0.f, a2 = 0.f, a3 = 0.f, ab = 0.f, ar = bias[o];
    const float* vrow = sv + nl * 16;
#pragma unroll
    for (int i = 0; i < 16; i++) {
        float vi = vrow[i];
        int j = i * 16 + o;
        const float* w4 = sw + j * 4;
        a0 = fmaf(vi, w4[0], a0);
        a1 = fmaf(vi, w4[1], a1);
        a2 = fmaf(vi, w4[2], a2);
        a3 = fmaf(vi, w4[3], a3);
        ab = fmaf(vi, sb[j], ab);
        ar = fmaf(vi, sroot[j], ar);
    }
    __half2 h01 = __floats2half2_rn(a0, a1);
    __half2 h23 = __floats2half2_rn(a2, a3);
    uint2 pk;
    pk.x = *reinterpret_cast<unsigned*>(&h01);
    pk.y = *reinterpret_cast<unsigned*>(&h23);
    *reinterpret_cast<uint2*>(g_t + (size_t)n * 64 + o * 4) = pk;
    g_tb[n * 16 + o] = __float2half_rn(ab);
    g_r[n * 16 + o] = ar;
}

// ---------------------------------------------------------------------------
// K2: degree histogram over dst
// ---------------------------------------------------------------------------
__global__ void __launch_bounds__(256) k_hist(const int* __restrict__ ei) {
    int e = blockIdx.x * 256 + threadIdx.x;
    if (e < N_EDGES) atomicAdd(&g_deg[ei[N_EDGES + e]], 1);
}

// ---------------------------------------------------------------------------
// K3: per-block exclusive scan of degrees (1024-elem chunks)
// ---------------------------------------------------------------------------
__global__ void __launch_bounds__(1024) k_scan1() {
    __shared__ int s[1024];
    int t = threadIdx.x;
    int i = blockIdx.x * 1024 + t;
    int v = (i < N_NODES) ? g_deg[i] : 0;
    s[t] = v;
    __syncthreads();
#pragma unroll
    for (int off = 1; off < 1024; off <<= 1) {
        int x = (t >= off) ? s[t - off] : 0;
        __syncthreads();
        s[t] += x;
        __syncthreads();
    }
    if (i < N_NODES) g_rowstart[i] = s[t] - v;     // exclusive
    if (t == 1023) g_blocksum[blockIdx.x] = s[t];
}

// ---------------------------------------------------------------------------
// K4: add cross-block offsets; materialize rowstart + cursor
// ---------------------------------------------------------------------------
__global__ void __launch_bounds__(1024) k_fixup() {
    __shared__ int sb[128];
    int b = blockIdx.x;
    int t = threadIdx.x;
    if (t < 128) sb[t] = (t < b && t < NB_SCAN) ? g_blocksum[t] : 0;
    __syncthreads();
#pragma unroll
    for (int s = 64; s >= 1; s >>= 1) {
        if (t < s) sb[t] += sb[t + s];
        __syncthreads();
    }
    int i = b * 1024 + t;
    if (i < N_NODES) {
        int rs = g_rowstart[i] + sb[0];
        g_rowstart[i] = rs;
        g_cursor[i] = rs;
    }
}

// ---------------------------------------------------------------------------
// K5: scatter {src, eid} into dst-sorted perm array
// ---------------------------------------------------------------------------
__global__ void __launch_bounds__(256) k_scatter(const int* __restrict__ ei) {
    int e = blockIdx.x * 256 + threadIdx.x;
    if (e >= N_EDGES) return;
    int src = ei[e];
    int dst = ei[N_EDGES + e];
    int pos = atomicAdd(&g_cursor[dst], 1);
    g_perm[pos] = make_uint2((unsigned)src, (unsigned)e);
}

// ---------------------------------------------------------------------------
// K6: gather — 8 threads per node, each accumulates outputs o=2j, 2j+1.
// Replaces edge-RED + finalize: out = msg_sum/max(deg,1) + r; BN stats inline.
// ---------------------------------------------------------------------------
__global__ void __launch_bounds__(256) k_gather(
    const float* __restrict__ efeat,
    float* __restrict__ out)
{
    int t = threadIdx.x;
    int gid = blockIdx.x * 256 + t;
    int n = gid >> 3;
    int j = gid & 7;          // == t & 7 (256 % 8 == 0)

    float a0 = 0.f, a1 = 0.f;
    int beg = 0, deg = 0;
    if (n < N_NODES) { beg = g_rowstart[n]; deg = g_deg[n]; }
    int end = beg + deg;

    const float4* ef4 = reinterpret_cast<const float4*>(efeat);

    uint2 es = (deg > 0) ? g_perm[beg] : make_uint2(0u, 0u);
    for (int p = beg; p < end; p++) {
        uint2 cur = es;
        int pn = p + 1;
        if (pn < end) es = g_perm[pn];                 // prefetch next
        float4 ev = __ldg(ef4 + cur.y);
        uint4 traw = __ldg(reinterpret_cast<const uint4*>(g_t + (size_t)cur.x * 64 + j * 8));
        unsigned tbraw = __ldg(reinterpret_cast<const unsigned*>(g_tb + (size_t)cur.x * 16 + j * 2));
        __half2 h0 = *reinterpret_cast<__half2*>(&traw.x);
        __half2 h1 = *reinterpret_cast<__half2*>(&traw.y);
        __half2 h2 = *reinterpret_cast<__half2*>(&traw.z);
        __half2 h3 = *reinterpret_cast<__half2*>(&traw.w);
        __half2 tbh = *reinterpret_cast<__half2*>(&tbraw);
        float2 c0 = __half22float2(h0);
        float2 c1 = __half22float2(h1);
        float2 c2 = __half22float2(h2);
        float2 c3 = __half22float2(h3);
        float2 tbf = __half22float2(tbh);
        a0 += fmaf(ev.x, c0.x, fmaf(ev.y, c0.y, fmaf(ev.z, c1.x, fmaf(ev.w, c1.y, tbf.x))));
        a1 += fmaf(ev.x, c2.x, fmaf(ev.y, c2.y, fmaf(ev.z, c3.x, fmaf(ev.w, c3.y, tbf.y))));
    }

    float v0 = 0.f, v1 = 0.f;
    if (n < N_NODES) {
        float inv = 1.0f / fmaxf((float)deg, 1.0f);
        float2 r = *reinterpret_cast<const float2*>(g_r + (size_t)n * 16 + j * 2);
        v0 = fmaf(a0, inv, r.x);
        v1 = fmaf(a1, inv, r.y);
        *reinterpret_cast<float2*>(out + (size_t)n * 16 + j * 2) = make_float2(v0, v1);
    }

    // BN stats: outputs o = 2j, 2j+1
    float s1a = v0, s1b = v1;
    float s2a = v0 * v0, s2b = v1 * v1;
    // combine lanes with same (lane & 7): xor 8, 16
#pragma unroll
    for (int m = 8; m <= 16; m <<= 1) {
        s1a += __shfl_xor_sync(0xffffffffu, s1a, m);
        s1b += __shfl_xor_sync(0xffffffffu, s1b, m);
        s2a += __shfl_xor_sync(0xffffffffu, s2a, m);
        s2b += __shfl_xor_sync(0xffffffffu, s2b, m);
    }
    __shared__ float sm1[8][8][2];
    __shared__ float sm2[8][8][2];
    int warp = t >> 5;
    int lane = t & 31;
    if (lane < 8) {
        sm1[warp][lane][0] = s1a; sm1[warp][lane][1] = s1b;
        sm2[warp][lane][0] = s2a; sm2[warp][lane][1] = s2b;
    }
    __syncthreads();
    if (t < 16) {       // o = t; j = t>>1, comp = t&1
        float r1 = 0.f, r2 = 0.f;
#pragma unroll
        for (int w = 0; w < 8; w++) {
            r1 += sm1[w][t >> 1][t & 1];
            r2 += sm2[w][t >> 1][t & 1];
        }
        atomicAdd(&g_s1[t], r1);
        atomicAdd(&g_s2[t], r2);
    }
}

// ---------------------------------------------------------------------------
// K7: BatchNorm (batch stats) + LeakyReLU, float4 in-place.
// ---------------------------------------------------------------------------
__global__ void __launch_bounds__(256) k_bn(
    float* __restrict__ out,
    const float* __restrict__ gamma,
    const float* __restrict__ beta)
{
    int i = blockIdx.x * 256 + threadIdx.x;
    if (i >= N_NODES * 4) return;
    int ob = (i & 3) * 4;
    const float invN = 1.0f / (float)N_NODES;

    float4* o4 = reinterpret_cast<float4*>(out);
    float4 val = o4[i];
    float vin[4] = {val.x, val.y, val.z, val.w};
    float res[4];
#pragma unroll
    for (int k = 0; k < 4; k++) {
        int o = ob + k;
        float mu = g_s1[o] * invN;
        float var = g_s2[o] * invN - mu * mu;
        float x = gamma[o] * (vin[k] - mu) * rsqrtf(var + 1e-5f) + beta[o];
        res[k] = (x >= 0.0f) ? x : 0.01f * x;
    }
    o4[i] = make_float4(res[0], res[1], res[2], res[3]);
}

// ---------------------------------------------------------------------------
extern "C" void kernel_launch(void* const* d_in, const int* in_sizes, int n_in,
                              void* d_out, int out_size) {
    const float* v      = (const float*)d_in[0];
    const float* e      = (const float*)d_in[1];
    const int*   ei     = (const int*)  d_in[2];
    const float* enet_w = (const float*)d_in[3];
    const float* enet_b = (const float*)d_in[4];
    const float* root   = (const float*)d_in[5];
    const float* bias   = (const float*)d_in[6];
    const float* gamma  = (const float*)d_in[7];
    const float* beta   = (const float*)d_in[8];
    float* out = (float*)d_out;

    k_zero    <<<(N_NODES + 255) / 256, 256>>>();
    k_node_pre<<<(N_NODES + 15) / 16, 256>>>(v, enet_w, enet_b, root, bias);
    k_hist    <<<(N_EDGES + 255) / 256, 256>>>(ei);
    k_scan1   <<<NB_SCAN, 1024>>>();
    k_fixup   <<<NB_SCAN, 1024>>>();
    k_scatter <<<(N_EDGES + 255) / 256, 256>>>(ei);
    k_gather  <<<(N_NODES * 8 + 255) / 256, 256>>>(e, out);
    k_bn      <<<(N_NODES * 4 + 255) / 256, 256>>>(out, gamma, beta);
}

// round 6
// speedup vs baseline: 1.3275x; 1.3275x over previous
#include <cuda_runtime.h>
#include <cuda_fp16.h>

#define N_NODES 100000
#define N_EDGES 1000000

__device__ __half g_t[N_NODES * 64];    // [n][o][c] fp16: t[n,o,c] = sum_i v[n,i]*W[i*16+o][c]
__device__ __half g_tb[N_NODES * 16];   // [n][o]    fp16: tb[n,o] = sum_i v[n,i]*b[i*16+o]
__device__ float  g_r[N_NODES * 16];    // [n][o]    fp32: v@root + bias (node-local term)
__device__ float  g_sum[N_NODES * 16];  // scatter accumulator
__device__ float  g_cnt[N_NODES];       // degree accumulator
__device__ float  g_s1[16];             // batch sum per feature
__device__ float  g_s2[16];             // batch sum-of-squares per feature

// ---------------------------------------------------------------------------
// K0: zero accumulators (float4 stores)
// ---------------------------------------------------------------------------
__global__ void __launch_bounds__(256) k_zero() {
    int idx = blockIdx.x * blockDim.x + threadIdx.x;
    int stride = gridDim.x * blockDim.x;
    float4* s4 = reinterpret_cast<float4*>(g_sum);
    const float4 z = make_float4(0.f, 0.f, 0.f, 0.f);
    for (int i = idx; i < N_NODES * 4; i += stride) s4[i] = z;
    for (int i = idx; i < N_NODES; i += stride) g_cnt[i] = 0.0f;
    if (idx < 16) { g_s1[idx] = 0.0f; g_s2[idx] = 0.0f; }
}

// ---------------------------------------------------------------------------
// K1: per-node precompute of t (fp16), tb (fp16), and r = v@root + bias (fp32).
// ---------------------------------------------------------------------------
__global__ void __launch_bounds__(256) k_node_pre(
    const float* __restrict__ v,
    const float* __restrict__ enet_w,   // [256][4]
    const float* __restrict__ enet_b,   // [256]
    const float* __restrict__ root,     // [16][16] (i,o)
    const float* __restrict__ bias)     // [16]
{
    __shared__ float sw[1024];
    __shared__ float sb[256];
    __shared__ float sroot[256];
    __shared__ float sv[256];
    int t = threadIdx.x;
    for (int i = t; i < 1024; i += 256) sw[i] = enet_w[i];
    sb[t] = enet_b[t];
    sroot[t] = root[t];
    int nbase = blockIdx.x * 16;
    sv[t] = v[nbase * 16 + t];
    __syncthreads();

    int nl = t >> 4;
    int o = t & 15;
    int n = nbase + nl;
    if (n >= N_NODES) return;

    float a0 = 0.f, a1 = 0.f, a2 = 0.f, a3 = 0.f, ab = 0.f, ar = bias[o];
    const float* vrow = sv + nl * 16;
#pragma unroll
    for (int i = 0; i < 16; i++) {
        float vi = vrow[i];
        int j = i * 16 + o;
        const float* w4 = sw + j * 4;
        a0 = fmaf(vi, w4[0], a0);
        a1 = fmaf(vi, w4[1], a1);
        a2 = fmaf(vi, w4[2], a2);
        a3 = fmaf(vi, w4[3], a3);
        ab = fmaf(vi, sb[j], ab);
        ar = fmaf(vi, sroot[j], ar);
    }
    __half2 h01 = __floats2half2_rn(a0, a1);
    __half2 h23 = __floats2half2_rn(a2, a3);
    uint2 pk;
    pk.x = *reinterpret_cast<unsigned*>(&h01);
    pk.y = *reinterpret_cast<unsigned*>(&h23);
    *reinterpret_cast<uint2*>(g_t + (size_t)n * 64 + o * 4) = pk;
    g_tb[n * 16 + o] = __float2half_rn(ab);
    g_r[n * 16 + o] = ar;
}

// ---------------------------------------------------------------------------
// K2: per-edge message + vector RED scatter. 2 edges per thread for ILP.
// Quad of 4 threads handles edges (2p, 2p+1); thread j covers outputs 4j..4j+3.
// ---------------------------------------------------------------------------
__global__ void __launch_bounds__(256) k_edge(
    const float* __restrict__ efeat,
    const int* __restrict__ ei)   // [2][E] row0=src, row1=dst
{
    int gid = blockIdx.x * 256 + threadIdx.x;
    int pair = gid >> 2;
    int j = gid & 3;
    int e0 = pair * 2;
    if (e0 >= N_EDGES) return;
    int e1 = e0 + 1;

    // indices: e0 even -> int2 loads are 8B aligned
    int2 srcs = *reinterpret_cast<const int2*>(ei + e0);
    int2 dsts = *reinterpret_cast<const int2*>(ei + N_EDGES + e0);

    const float4* ef4 = reinterpret_cast<const float4*>(efeat);
    float4 ev0 = __ldg(ef4 + e0);
    float4 ev1 = __ldg(ef4 + e1);

    // independent gathers for both edges
    const uint4* tp0 = reinterpret_cast<const uint4*>(g_t + (size_t)srcs.x * 64 + j * 16);
    const uint4* tp1 = reinterpret_cast<const uint4*>(g_t + (size_t)srcs.y * 64 + j * 16);
    uint4 ta0 = __ldg(tp0);
    uint4 ta1 = __ldg(tp0 + 1);
    uint4 tb0 = __ldg(tp1);
    uint4 tb1 = __ldg(tp1 + 1);
    uint2 tbr0 = __ldg(reinterpret_cast<const uint2*>(g_tb + (size_t)srcs.x * 16 + j * 4));
    uint2 tbr1 = __ldg(reinterpret_cast<const uint2*>(g_tb + (size_t)srcs.y * 16 + j * 4));

#define H2F(u) __half22float2(*reinterpret_cast<__half2*>(&(u)))
    {
        float2 b01 = H2F(tbr0.x), b23 = H2F(tbr0.y);
        float2 c0 = H2F(ta0.x), c1 = H2F(ta0.y), c2 = H2F(ta0.z), c3 = H2F(ta0.w);
        float2 c4 = H2F(ta1.x), c5 = H2F(ta1.y), c6 = H2F(ta1.z), c7 = H2F(ta1.w);
        float m0 = fmaf(ev0.x, c0.x, fmaf(ev0.y, c0.y, fmaf(ev0.z, c1.x, fmaf(ev0.w, c1.y, b01.x))));
        float m1 = fmaf(ev0.x, c2.x, fmaf(ev0.y, c2.y, fmaf(ev0.z, c3.x, fmaf(ev0.w, c3.y, b01.y))));
        float m2 = fmaf(ev0.x, c4.x, fmaf(ev0.y, c4.y, fmaf(ev0.z, c5.x, fmaf(ev0.w, c5.y, b23.x))));
        float m3 = fmaf(ev0.x, c6.x, fmaf(ev0.y, c6.y, fmaf(ev0.z, c7.x, fmaf(ev0.w, c7.y, b23.y))));
        float* outp = g_sum + (size_t)dsts.x * 16 + j * 4;
        asm volatile("red.global.add.v4.f32 [%0], {%1, %2, %3, %4};"
                     :: "l"(outp), "f"(m0), "f"(m1), "f"(m2), "f"(m3) : "memory");
    }
    {
        float2 b01 = H2F(tbr1.x), b23 = H2F(tbr1.y);
        float2 c0 = H2F(tb0.x), c1 = H2F(tb0.y), c2 = H2F(tb0.z), c3 = H2F(tb0.w);
        float2 c4 = H2F(tb1.x), c5 = H2F(tb1.y), c6 = H2F(tb1.z), c7 = H2F(tb1.w);
        float m0 = fmaf(ev1.x, c0.x, fmaf(ev1.y, c0.y, fmaf(ev1.z, c1.x, fmaf(ev1.w, c1.y, b01.x))));
        float m1 = fmaf(ev1.x, c2.x, fmaf(ev1.y, c2.y, fmaf(ev1.z, c3.x, fmaf(ev1.w, c3.y, b01.y))));
        float m2 = fmaf(ev1.x, c4.x, fmaf(ev1.y, c4.y, fmaf(ev1.z, c5.x, fmaf(ev1.w, c5.y, b23.x))));
        float m3 = fmaf(ev1.x, c6.x, fmaf(ev1.y, c6.y, fmaf(ev1.z, c7.x, fmaf(ev1.w, c7.y, b23.y))));
        float* outp = g_sum + (size_t)dsts.y * 16 + j * 4;
        asm volatile("red.global.add.v4.f32 [%0], {%1, %2, %3, %4};"
                     :: "l"(outp), "f"(m0), "f"(m1), "f"(m2), "f"(m3) : "memory");
    }
#undef H2F
    if (j == 0) {
        atomicAdd(g_cnt + dsts.x, 1.0f);
        atomicAdd(g_cnt + dsts.y, 1.0f);
    }
}

// ---------------------------------------------------------------------------
// K3: finalize pre-BN output — one float4 per thread, fully independent loads.
// out[n,o] = g_sum[n,o]/max(cnt,1) + g_r[n,o]; BN stats accumulated inline.
// ---------------------------------------------------------------------------
__global__ void __launch_bounds__(256) k_final(float* __restrict__ out)
{
    int t = threadIdx.x;
    int i = blockIdx.x * 256 + t;
    bool active = (i < N_NODES * 4);

    float4 val = make_float4(0.f, 0.f, 0.f, 0.f);
    if (active) {
        int n = i >> 2;
        float inv = 1.0f / fmaxf(g_cnt[n], 1.0f);
        float4 s = reinterpret_cast<const float4*>(g_sum)[i];
        float4 r = reinterpret_cast<const float4*>(g_r)[i];
        val.x = fmaf(s.x, inv, r.x);
        val.y = fmaf(s.y, inv, r.y);
        val.z = fmaf(s.z, inv, r.z);
        val.w = fmaf(s.w, inv, r.w);
        reinterpret_cast<float4*>(out)[i] = val;
    }

    float s1x = val.x, s1y = val.y, s1z = val.z, s1w = val.w;
    float s2x = val.x * val.x, s2y = val.y * val.y;
    float s2z = val.z * val.z, s2w = val.w * val.w;

    // combine lanes with same (lane & 3): xor 4, 8, 16
#pragma unroll
    for (int m = 4; m <= 16; m <<= 1) {
        s1x += __shfl_xor_sync(0xffffffffu, s1x, m);
        s1y += __shfl_xor_sync(0xffffffffu, s1y, m);
        s1z += __shfl_xor_sync(0xffffffffu, s1z, m);
        s1w += __shfl_xor_sync(0xffffffffu, s1w, m);
        s2x += __shfl_xor_sync(0xffffffffu, s2x, m);
        s2y += __shfl_xor_sync(0xffffffffu, s2y, m);
        s2z += __shfl_xor_sync(0xffffffffu, s2z, m);
        s2w += __shfl_xor_sync(0xffffffffu, s2w, m);
    }

    __shared__ float sm1[8][4][4];
    __shared__ float sm2[8][4][4];
    int warp = t >> 5;
    int lane = t & 31;
    if (lane < 4) {   // lane = jpos; o = 4*lane + comp
        sm1[warp][lane][0] = s1x; sm1[warp][lane][1] = s1y;
        sm1[warp][lane][2] = s1z; sm1[warp][lane][3] = s1w;
        sm2[warp][lane][0] = s2x; sm2[warp][lane][1] = s2y;
        sm2[warp][lane][2] = s2z; sm2[warp][lane][3] = s2w;
    }
    __syncthreads();
    if (t < 16) {   // o = t; jpos = t>>2, comp = t&3
        float a1 = 0.f, a2 = 0.f;
#pragma unroll
        for (int w = 0; w < 8; w++) {
            a1 += sm1[w][t >> 2][t & 3];
            a2 += sm2[w][t >> 2][t & 3];
        }
        atomicAdd(&g_s1[t], a1);
        atomicAdd(&g_s2[t], a2);
    }
}

// ---------------------------------------------------------------------------
// K4: BatchNorm (batch stats) + LeakyReLU, float4 in-place.
// ---------------------------------------------------------------------------
__global__ void __launch_bounds__(256) k_bn(
    float* __restrict__ out,
    const float* __restrict__ gamma,
    const float* __restrict__ beta)
{
    int i = blockIdx.x * 256 + threadIdx.x;
    if (i >= N_NODES * 4) return;
    int ob = (i & 3) * 4;
    const float invN = 1.0f / (float)N_NODES;

    float4* o4 = reinterpret_cast<float4*>(out);
    float4 val = o4[i];
    float vin[4] = {val.x, val.y, val.z, val.w};
    float res[4];
#pragma unroll
    for (int k = 0; k < 4; k++) {
        int o = ob + k;
        float mu = g_s1[o] * invN;
        float var = g_s2[o] * invN - mu * mu;
        float x = gamma[o] * (vin[k] - mu) * rsqrtf(var + 1e-5f) + beta[o];
        res[k] = (x >= 0.0f) ? x : 0.01f * x;
    }
    o4[i] = make_float4(res[0], res[1], res[2], res[3]);
}

// ---------------------------------------------------------------------------
extern "C" void kernel_launch(void* const* d_in, const int* in_sizes, int n_in,
                              void* d_out, int out_size) {
    const float* v      = (const float*)d_in[0];
    const float* e      = (const float*)d_in[1];
    const int*   ei     = (const int*)  d_in[2];
    const float* enet_w = (const float*)d_in[3];
    const float* enet_b = (const float*)d_in[4];
    const float* root   = (const float*)d_in[5];
    const float* bias   = (const float*)d_in[6];
    const float* gamma  = (const float*)d_in[7];
    const float* beta   = (const float*)d_in[8];
    float* out = (float*)d_out;

    k_zero    <<<592, 256>>>();
    k_node_pre<<<(N_NODES + 15) / 16, 256>>>(v, enet_w, enet_b, root, bias);
    k_edge    <<<(N_EDGES / 2 * 4 + 255) / 256, 256>>>(e, ei);
    k_final   <<<(N_NODES * 4 + 255) / 256, 256>>>(out);
    k_bn      <<<(N_NODES * 4 + 255) / 256, 256>>>(out, gamma, beta);
}